// round 4
// baseline (speedup 1.0000x reference)
#include <cuda_runtime.h>
#include <cuda_bf16.h>
#include <cstdint>

#define NN 50000
#define NE 800000
#define NF 96
#define NC 40

// ---------------- flat static device scratch ----------------
#define OFF_DEG      0
#define OFF_DINV     (OFF_DEG + NN)
#define OFF_COUNTS   (OFF_DINV + NN)
#define OFF_CURSOR   (OFF_COUNTS + NN)
#define OFF_OFFSETS  (OFF_CURSOR + NN)            // NN+1 ints
#define OFF_FLAGS    (OFF_OFFSETS + NN + 4)       // 4 ints: dtype flags
#define OFF_SRC      (OFF_FLAGS + 12)             // keep 16B alignment
#define OFF_NORM     (OFF_SRC + NE)
#define OFF_EW       (OFF_NORM + NE)
#define OFF_H0       (OFF_EW + NE)
#define OFF_H1       (OFF_H0 + NN * NF)
#define OFF_L0       (OFF_H1 + NN * NF)
#define OFF_L1       (OFF_L0 + NN * NC)
#define SCRATCH_ELEMS (OFF_L1 + NN * NC)

__device__ __align__(256) float g_scratch[SCRATCH_ELEMS];

// ---------------- dtype helpers ----------------
// flags[0]: edge_index is int64 (1) or int32 (0)
// flags[1]: mask is 4-byte (1) or 1-byte (0)
// flags[2]: y is int64 (1) or int32 (0)

__device__ __forceinline__ int load_idx(const void* p, long long i, int is64) {
    return is64 ? (int)((const long long*)p)[i] : ((const int*)p)[i];
}

// ---------------- kernels ----------------

__global__ void init_kernel(float* __restrict__ deg, int* __restrict__ counts,
                            int* __restrict__ flags) {
    int i = blockIdx.x * blockDim.x + threadIdx.x;
    if (i < NN) {
        deg[i] = 1.0f;   // self-loop contributes 1 to deg[col]
        counts[i] = 0;
    }
    if (i < 3) flags[i] = 1;  // assume wide until disproven
}

// Deterministic byte-level dtype sniff. Safe reads for either dtype:
//   ei buffer >= 2*NE*4 = 6.4MB, we read 8KB.  y >= 200KB, read 8KB.  mask >= 50KB, read 4KB.
// If ei is int64 (values < 50000 < 2^32) every odd 32-bit word is 0.
// If int32, 1024 random indices in [0,50000) are never all zero.
__global__ void sniff_kernel(const void* __restrict__ ei,
                             const void* __restrict__ y,
                             const void* __restrict__ mask,
                             int* __restrict__ flags) {
    int t = blockIdx.x * blockDim.x + threadIdx.x;
    const int* ei32 = (const int*)ei;
    const int* y32  = (const int*)y;
    const unsigned char* m8 = (const unsigned char*)mask;
    if (t < 1024) {
        if (ei32[2 * t + 1] != 0) flags[0] = 0;
        if (y32[2 * t + 1]  != 0) flags[2] = 0;
    }
    if (t < 4096) {
        if ((t & 3) != 0 && m8[t] != 0) flags[1] = 0;  // nonzero pad byte -> 1-byte mask
    }
}

__global__ void deg_count_kernel(const void* __restrict__ ei,
                                 const float* __restrict__ ew,
                                 float* __restrict__ deg,
                                 int* __restrict__ counts,
                                 const int* __restrict__ flags) {
    int e = blockIdx.x * blockDim.x + threadIdx.x;
    if (e < NE) {
        int is64 = flags[0];
        int c = load_idx(ei, (long long)NE + e, is64);
        if ((unsigned)c < NN) {
            atomicAdd(&deg[c], ew[e]);
            atomicAdd(&counts[c], 1);
        }
    }
}

__global__ void dinv_kernel(const float* __restrict__ deg,
                            float* __restrict__ dinv) {
    int i = blockIdx.x * blockDim.x + threadIdx.x;
    if (i < NN) dinv[i] = rsqrtf(deg[i]);  // deg >= 1 always
}

// single-block exclusive scan of counts -> offsets (N=50000)
__global__ __launch_bounds__(1024) void scan_kernel(const int* __restrict__ counts,
                                                    int* __restrict__ offsets,
                                                    int* __restrict__ cursor) {
    __shared__ int sh[1024];
    __shared__ int carry;
    if (threadIdx.x == 0) carry = 0;
    __syncthreads();
    for (int base = 0; base < NN; base += 1024) {
        int i = base + threadIdx.x;
        int v = (i < NN) ? counts[i] : 0;
        sh[threadIdx.x] = v;
        __syncthreads();
        for (int off = 1; off < 1024; off <<= 1) {
            int t = (threadIdx.x >= off) ? sh[threadIdx.x - off] : 0;
            __syncthreads();
            sh[threadIdx.x] += t;
            __syncthreads();
        }
        if (i < NN) {
            int excl = carry + sh[threadIdx.x] - v;
            offsets[i] = excl;
            cursor[i]  = excl;
        }
        __syncthreads();
        if (threadIdx.x == 1023) carry += sh[1023];
        __syncthreads();
    }
    if (threadIdx.x == 0) offsets[NN] = carry;
}

__global__ void fill_kernel(const void* __restrict__ ei,
                            const float* __restrict__ ew,
                            const float* __restrict__ dinv,
                            int* __restrict__ cursor,
                            int* __restrict__ src,
                            float* __restrict__ norm,
                            float* __restrict__ ew2,
                            const int* __restrict__ flags) {
    int e = blockIdx.x * blockDim.x + threadIdx.x;
    if (e < NE) {
        int is64 = flags[0];
        int r = load_idx(ei, e, is64);
        int c = load_idx(ei, (long long)NE + e, is64);
        if ((unsigned)r < NN && (unsigned)c < NN) {
            int pos = atomicAdd(&cursor[c], 1);
            if ((unsigned)pos < NE) {
                float w = ew[e];
                src[pos]  = r;
                norm[pos] = dinv[r] * w * dinv[c];
                ew2[pos]  = w;
            }
        }
    }
}

// SGC propagate: out[n] = dinv[n]^2 * in[n] + sum_{e->n} norm[e] * in[src[e]]
// one warp per node, 3 features per lane (96 = 3*32)
__global__ void sgc_prop_kernel(const float* __restrict__ in,
                                float* __restrict__ out,
                                const float* __restrict__ dinv,
                                const int* __restrict__ offsets,
                                const int* __restrict__ src,
                                const float* __restrict__ norm) {
    int warp = (blockIdx.x * blockDim.x + threadIdx.x) >> 5;
    int lane = threadIdx.x & 31;
    if (warp >= NN) return;
    int n = warp;
    float dii = dinv[n];
    dii *= dii;
    const float* rp = in + (size_t)n * NF;
    float a0 = dii * rp[lane];
    float a1 = dii * rp[lane + 32];
    float a2 = dii * rp[lane + 64];
    int beg = offsets[n], end = offsets[n + 1];
    for (int e = beg; e < end; e++) {
        int s   = src[e];
        float w = norm[e];
        const float* sp = in + (size_t)s * NF;
        a0 += w * sp[lane];
        a1 += w * sp[lane + 32];
        a2 += w * sp[lane + 64];
    }
    float* op = out + (size_t)n * NF;
    op[lane]      = a0;
    op[lane + 32] = a1;
    op[lane + 64] = a2;
}

// x_out = h @ W + b   (50000x96 @ 96x40), 64 rows per block of 256 threads
__global__ void gemm_kernel(const float* __restrict__ h,
                            const float* __restrict__ W,
                            const float* __restrict__ b,
                            float* __restrict__ out) {
    __shared__ float sW[NF * NC];   // 15360 B
    __shared__ float sH[64 * NF];   // 24576 B
    int tid = threadIdx.x;
    int row0 = blockIdx.x * 64;

    for (int i = tid; i < NF * NC; i += 256) sW[i] = W[i];

    int nrows = min(64, NN - row0);
    int nelem = nrows * NF;
    const float* hp = h + (size_t)row0 * NF;   // contiguous tile
    for (int i = tid; i < nelem; i += 256) sH[i] = hp[i];
    __syncthreads();

    int nout = nrows * NC;
    for (int o = tid; o < nout; o += 256) {
        int r = o / NC, c = o % NC;
        float acc = b[c];
        const float* hr = &sH[r * NF];
        #pragma unroll 8
        for (int k = 0; k < NF; k++) acc += hr[k] * sW[k * NC + c];
        out[(size_t)(row0 + r) * NC + c] = acc;
    }
}

__global__ void lpa_init_kernel(const void* __restrict__ y,
                                const void* __restrict__ mask,
                                float* __restrict__ l0,
                                const int* __restrict__ flags) {
    int idx = blockIdx.x * blockDim.x + threadIdx.x;
    if (idx < NN * NC) {
        int n = idx / NC, c = idx % NC;
        int yv = load_idx(y, n, flags[2]);
        int mv = flags[1] ? ((const int*)mask)[n] : (int)((const unsigned char*)mask)[n];
        l0[idx] = (mv != 0 && yv == c) ? 1.0f : 0.0f;
    }
}

// LPA propagate: out[n] = sum_{e->n} ew[e] * in[src[e]]  (no self-loops)
// one warp per node; 40 = 32 + 8
__global__ void lpa_prop_kernel(const float* __restrict__ in,
                                float* __restrict__ out,
                                const int* __restrict__ offsets,
                                const int* __restrict__ src,
                                const float* __restrict__ ew2) {
    int warp = (blockIdx.x * blockDim.x + threadIdx.x) >> 5;
    int lane = threadIdx.x & 31;
    if (warp >= NN) return;
    int n = warp;
    float a0 = 0.0f, a1 = 0.0f;
    int beg = offsets[n], end = offsets[n + 1];
    for (int e = beg; e < end; e++) {
        int s   = src[e];
        float w = ew2[e];
        const float* sp = in + (size_t)s * NC;
        a0 += w * sp[lane];
        if (lane < 8) a1 += w * sp[32 + lane];
    }
    float* op = out + (size_t)n * NC;
    op[lane] = a0;
    if (lane < 8) op[32 + lane] = a1;
}

// ---------------- launch ----------------

extern "C" void kernel_launch(void* const* d_in, const int* in_sizes, int n_in,
                              void* d_out, int out_size) {
    const float* x    = (const float*)d_in[0];
    const void*  ei   = d_in[1];
    const void*  y    = d_in[2];
    const void*  mask = d_in[3];
    const float* ew   = (const float*)d_in[4];
    const float* W    = (const float*)d_in[5];
    const float* b    = (const float*)d_in[6];
    float* out = (float*)d_out;
    float* x_out   = out;             // [NN, NC]
    float* lpa_out = out + NN * NC;   // [NN, NC]

    static float* s = nullptr;
    if (s == nullptr) {
        void* p = nullptr;
        cudaGetSymbolAddress(&p, g_scratch);
        s = (float*)p;
    }
    float* deg     = s + OFF_DEG;
    float* dinv    = s + OFF_DINV;
    int*   counts  = (int*)(s + OFF_COUNTS);
    int*   cursor  = (int*)(s + OFF_CURSOR);
    int*   offsets = (int*)(s + OFF_OFFSETS);
    int*   flags   = (int*)(s + OFF_FLAGS);
    int*   src     = (int*)(s + OFF_SRC);
    float* norm    = s + OFF_NORM;
    float* ew2     = s + OFF_EW;
    float* h0      = s + OFF_H0;
    float* h1      = s + OFF_H1;
    float* l0      = s + OFF_L0;
    float* l1      = s + OFF_L1;

    const int TB = 256;
    int gN = (NN + TB - 1) / TB;
    int gE = (NE + TB - 1) / TB;
    int gWarpN = (NN * 32 + TB - 1) / TB;   // one warp per node

    // ---- dtype sniff + CSR build ----
    init_kernel<<<gN, TB>>>(deg, counts, flags);
    sniff_kernel<<<16, 256>>>(ei, y, mask, flags);
    deg_count_kernel<<<gE, TB>>>(ei, ew, deg, counts, flags);
    dinv_kernel<<<gN, TB>>>(deg, dinv);
    scan_kernel<<<1, 1024>>>(counts, offsets, cursor);
    fill_kernel<<<gE, TB>>>(ei, ew, dinv, cursor, src, norm, ew2, flags);

    // ---- SGConv K=2 ----
    sgc_prop_kernel<<<gWarpN, TB>>>(x,  h0, dinv, offsets, src, norm);
    sgc_prop_kernel<<<gWarpN, TB>>>(h0, h1, dinv, offsets, src, norm);
    gemm_kernel<<<(NN + 63) / 64, 256>>>(h1, W, b, x_out);

    // ---- LPA 3 iters ----
    int gNC = (NN * NC + TB - 1) / TB;
    lpa_init_kernel<<<gNC, TB>>>(y, mask, l0, flags);
    lpa_prop_kernel<<<gWarpN, TB>>>(l0, l1, offsets, src, ew2);
    lpa_prop_kernel<<<gWarpN, TB>>>(l1, l0, offsets, src, ew2);
    lpa_prop_kernel<<<gWarpN, TB>>>(l0, lpa_out, offsets, src, ew2);

    (void)in_sizes; (void)n_in; (void)out_size;
}

// round 5
// speedup vs baseline: 1.0940x; 1.0940x over previous
#include <cuda_runtime.h>
#include <cuda_bf16.h>
#include <cstdint>

#define NN 50000
#define NE 800000
#define NF 96
#define NC 40

// ---------------- flat static device scratch ----------------
#define OFF_DEG      0
#define OFF_DINV     (OFF_DEG + NN)
#define OFF_COUNTS   (OFF_DINV + NN)
#define OFF_CURSOR   (OFF_COUNTS + NN)
#define OFF_OFFSETS  (OFF_CURSOR + NN)              // NN+1 ints
#define OFF_FLAGS    (OFF_OFFSETS + NN + 8)         // 4 ints
#define OFF_PAIR_SGC (OFF_FLAGS + 8)                // NE int2 (src, norm)
#define OFF_PAIR_LPA (OFF_PAIR_SGC + 2 * NE)        // NE int2 (src, ew)
#define OFF_H0       (OFF_PAIR_LPA + 2 * NE)
#define OFF_H1       (OFF_H0 + NN * NF)
#define OFF_L0       (OFF_H1 + NN * NF)
#define OFF_L1       (OFF_L0 + NN * NC)
#define SCRATCH_ELEMS (OFF_L1 + NN * NC + 64)       // +pad

__device__ __align__(256) float g_scratch[SCRATCH_ELEMS];

// flags[0]: edge_index is int64; flags[1]: mask is 4-byte; flags[2]: y is int64
__device__ __forceinline__ int load_idx(const void* p, long long i, int is64) {
    return is64 ? (int)((const long long*)p)[i] : ((const int*)p)[i];
}

// ---------------- init + dtype sniff (block 0 owns flags; no cross-block race) ----
__global__ void init_sniff_kernel(float* __restrict__ deg, int* __restrict__ counts,
                                  int* __restrict__ flags,
                                  const void* __restrict__ ei,
                                  const void* __restrict__ y,
                                  const void* __restrict__ mask) {
    int i = blockIdx.x * blockDim.x + threadIdx.x;
    if (i < NN) { deg[i] = 1.0f; counts[i] = 0; }

    if (blockIdx.x == 0) {
        __shared__ int narrow[3];
        int tid = threadIdx.x;
        if (tid < 3) narrow[tid] = 0;
        __syncthreads();
        const int* ei32 = (const int*)ei;
        const int* y32  = (const int*)y;
        const unsigned char* m8 = (const unsigned char*)mask;
        // If int64 (values < 2^32), every odd 32-bit word is 0. 256 samples.
        if (ei32[2 * tid + 1] != 0) narrow[0] = 1;
        if (y32[2 * tid + 1]  != 0) narrow[2] = 1;
        // If mask is 4-byte bool, pad bytes (pos % 4 != 0) are all 0.
        for (int t = tid; t < 4096; t += 256)
            if ((t & 3) != 0 && m8[t] != 0) narrow[1] = 1;
        __syncthreads();
        if (tid < 3) flags[tid] = narrow[tid] ? 0 : 1;
    }
}

__global__ void deg_count_kernel(const void* __restrict__ ei,
                                 const float* __restrict__ ew,
                                 float* __restrict__ deg,
                                 int* __restrict__ counts,
                                 const int* __restrict__ flags) {
    int e = blockIdx.x * blockDim.x + threadIdx.x;
    if (e < NE) {
        int c = load_idx(ei, (long long)NE + e, flags[0]);
        if ((unsigned)c < NN) {
            atomicAdd(&deg[c], ew[e]);
            atomicAdd(&counts[c], 1);
        }
    }
}

__global__ void dinv_kernel(const float* __restrict__ deg, float* __restrict__ dinv) {
    int i = blockIdx.x * blockDim.x + threadIdx.x;
    if (i < NN) dinv[i] = rsqrtf(deg[i]);
}

__global__ __launch_bounds__(1024) void scan_kernel(const int* __restrict__ counts,
                                                    int* __restrict__ offsets,
                                                    int* __restrict__ cursor) {
    __shared__ int sh[1024];
    __shared__ int carry;
    if (threadIdx.x == 0) carry = 0;
    __syncthreads();
    for (int base = 0; base < NN; base += 1024) {
        int i = base + threadIdx.x;
        int v = (i < NN) ? counts[i] : 0;
        sh[threadIdx.x] = v;
        __syncthreads();
        for (int off = 1; off < 1024; off <<= 1) {
            int t = (threadIdx.x >= off) ? sh[threadIdx.x - off] : 0;
            __syncthreads();
            sh[threadIdx.x] += t;
            __syncthreads();
        }
        if (i < NN) {
            int excl = carry + sh[threadIdx.x] - v;
            offsets[i] = excl;
            cursor[i]  = excl;
        }
        __syncthreads();
        if (threadIdx.x == 1023) carry += sh[1023];
        __syncthreads();
    }
    if (threadIdx.x == 0) offsets[NN] = carry;
}

// ---- fill CSR (+ fused LPA one-hot init in trailing blocks) ----
#define FILL_BLOCKS  ((NE + 255) / 256)             // 3125
#define LINIT_BLOCKS ((NN * NC + 255) / 256)        // 7813

__global__ void fill_lpainit_kernel(const void* __restrict__ ei,
                                    const float* __restrict__ ew,
                                    const float* __restrict__ dinv,
                                    int* __restrict__ cursor,
                                    int2* __restrict__ ps,   // (src, norm)
                                    int2* __restrict__ pl,   // (src, ew)
                                    const void* __restrict__ y,
                                    const void* __restrict__ mask,
                                    float* __restrict__ l0,
                                    const int* __restrict__ flags) {
    if (blockIdx.x < FILL_BLOCKS) {
        int e = blockIdx.x * blockDim.x + threadIdx.x;
        if (e < NE) {
            int is64 = flags[0];
            int r = load_idx(ei, e, is64);
            int c = load_idx(ei, (long long)NE + e, is64);
            if ((unsigned)r < NN && (unsigned)c < NN) {
                int pos = atomicAdd(&cursor[c], 1);
                if ((unsigned)pos < NE) {
                    float w = ew[e];
                    ps[pos] = make_int2(r, __float_as_int(dinv[r] * w * dinv[c]));
                    pl[pos] = make_int2(r, __float_as_int(w));
                }
            }
        }
    } else {
        int idx = (blockIdx.x - FILL_BLOCKS) * blockDim.x + threadIdx.x;
        if (idx < NN * NC) {
            int n = idx / NC, c = idx % NC;
            int yv = load_idx(y, n, flags[2]);
            int mv = flags[1] ? ((const int*)mask)[n]
                              : (int)((const unsigned char*)mask)[n];
            l0[idx] = (mv != 0 && yv == c) ? 1.0f : 0.0f;
        }
    }
}

// ---------------- propagate bodies (warp per node, unroll x4 for MLP) --------

__device__ __forceinline__ void sgc_body(int n, int lane,
                                         const float* __restrict__ in,
                                         float* __restrict__ out,
                                         const float* __restrict__ dinv,
                                         const int* __restrict__ offsets,
                                         const int2* __restrict__ pr) {
    float dii = dinv[n];
    dii *= dii;
    const float* rp = in + (size_t)n * NF;
    float a0 = dii * rp[lane];
    float a1 = dii * rp[lane + 32];
    float a2 = dii * rp[lane + 64];
    int e = offsets[n], end = offsets[n + 1];
    for (; e + 4 <= end; e += 4) {
        int2 p0 = pr[e], p1 = pr[e + 1], p2 = pr[e + 2], p3 = pr[e + 3];
        const float* q0 = in + (size_t)p0.x * NF;
        const float* q1 = in + (size_t)p1.x * NF;
        const float* q2 = in + (size_t)p2.x * NF;
        const float* q3 = in + (size_t)p3.x * NF;
        float w0 = __int_as_float(p0.y), w1 = __int_as_float(p1.y);
        float w2 = __int_as_float(p2.y), w3 = __int_as_float(p3.y);
        float b00 = q0[lane], b01 = q0[lane + 32], b02 = q0[lane + 64];
        float b10 = q1[lane], b11 = q1[lane + 32], b12 = q1[lane + 64];
        float b20 = q2[lane], b21 = q2[lane + 32], b22 = q2[lane + 64];
        float b30 = q3[lane], b31 = q3[lane + 32], b32 = q3[lane + 64];
        a0 += w0 * b00; a1 += w0 * b01; a2 += w0 * b02;
        a0 += w1 * b10; a1 += w1 * b11; a2 += w1 * b12;
        a0 += w2 * b20; a1 += w2 * b21; a2 += w2 * b22;
        a0 += w3 * b30; a1 += w3 * b31; a2 += w3 * b32;
    }
    for (; e < end; e++) {
        int2 p = pr[e];
        float w = __int_as_float(p.y);
        const float* sp = in + (size_t)p.x * NF;
        a0 += w * sp[lane]; a1 += w * sp[lane + 32]; a2 += w * sp[lane + 64];
    }
    float* op = out + (size_t)n * NF;
    op[lane] = a0; op[lane + 32] = a1; op[lane + 64] = a2;
}

__device__ __forceinline__ void lpa_body(int n, int lane,
                                         const float* __restrict__ in,
                                         float* __restrict__ out,
                                         const int* __restrict__ offsets,
                                         const int2* __restrict__ pr) {
    float a0 = 0.0f, a1 = 0.0f;
    int e = offsets[n], end = offsets[n + 1];
    for (; e + 4 <= end; e += 4) {
        int2 p0 = pr[e], p1 = pr[e + 1], p2 = pr[e + 2], p3 = pr[e + 3];
        const float* q0 = in + (size_t)p0.x * NC;
        const float* q1 = in + (size_t)p1.x * NC;
        const float* q2 = in + (size_t)p2.x * NC;
        const float* q3 = in + (size_t)p3.x * NC;
        float w0 = __int_as_float(p0.y), w1 = __int_as_float(p1.y);
        float w2 = __int_as_float(p2.y), w3 = __int_as_float(p3.y);
        float b0 = q0[lane], b1 = q1[lane], b2 = q2[lane], b3 = q3[lane];
        float c0 = 0.f, c1 = 0.f, c2 = 0.f, c3 = 0.f;
        if (lane < 8) {
            c0 = q0[32 + lane]; c1 = q1[32 + lane];
            c2 = q2[32 + lane]; c3 = q3[32 + lane];
        }
        a0 += w0 * b0 + w1 * b1 + w2 * b2 + w3 * b3;
        a1 += w0 * c0 + w1 * c1 + w2 * c2 + w3 * c3;
    }
    for (; e < end; e++) {
        int2 p = pr[e];
        float w = __int_as_float(p.y);
        const float* sp = in + (size_t)p.x * NC;
        a0 += w * sp[lane];
        if (lane < 8) a1 += w * sp[32 + lane];
    }
    float* op = out + (size_t)n * NC;
    op[lane] = a0;
    if (lane < 8) op[32 + lane] = a1;
}

// ---------------- fused role kernels ----------------
#define PROP_BLOCKS ((NN * 32 + 255) / 256)   // 6250 blocks (warp per node)

// K_A / K_B: blocks [0, PROP_BLOCKS) sgc, [PROP_BLOCKS, 2*PROP_BLOCKS) lpa
__global__ void prop_pair_kernel(const float* __restrict__ sgc_in,
                                 float* __restrict__ sgc_out,
                                 const float* __restrict__ lpa_in,
                                 float* __restrict__ lpa_out,
                                 const float* __restrict__ dinv,
                                 const int* __restrict__ offsets,
                                 const int2* __restrict__ ps,
                                 const int2* __restrict__ pl) {
    int lane = threadIdx.x & 31;
    int wib  = threadIdx.x >> 5;
    if (blockIdx.x < PROP_BLOCKS) {
        int n = blockIdx.x * 8 + wib;
        if (n < NN) sgc_body(n, lane, sgc_in, sgc_out, dinv, offsets, ps);
    } else {
        int n = (blockIdx.x - PROP_BLOCKS) * 8 + wib;
        if (n < NN) lpa_body(n, lane, lpa_in, lpa_out, offsets, pl);
    }
}

// K_C: blocks [0, GEMM_BLOCKS) gemm (32 rows each), rest lpa iter 3
#define GEMM_ROWS 32
#define GEMM_BLOCKS ((NN + GEMM_ROWS - 1) / GEMM_ROWS)   // 1563

__global__ void gemm_lpa_kernel(const float* __restrict__ h,
                                const float* __restrict__ W,
                                const float* __restrict__ b,
                                float* __restrict__ x_out,
                                const float* __restrict__ lpa_in,
                                float* __restrict__ lpa_out,
                                const int* __restrict__ offsets,
                                const int2* __restrict__ pl) {
    __shared__ float sW[NF * NC];          // 15360 B
    __shared__ float sH[GEMM_ROWS * NF];   // 12288 B
    if (blockIdx.x < GEMM_BLOCKS) {
        int tid = threadIdx.x;
        int row0 = blockIdx.x * GEMM_ROWS;
        for (int i = tid; i < NF * NC; i += 256) sW[i] = W[i];
        int nrows = min(GEMM_ROWS, NN - row0);
        int nelem = nrows * NF;
        const float* hp = h + (size_t)row0 * NF;
        for (int i = tid; i < nelem; i += 256) sH[i] = hp[i];
        __syncthreads();
        int nout = nrows * NC;
        for (int o = tid; o < nout; o += 256) {
            int r = o / NC, c = o % NC;
            float acc = b[c];
            const float* hr = &sH[r * NF];
            #pragma unroll 8
            for (int k = 0; k < NF; k++) acc += hr[k] * sW[k * NC + c];
            x_out[(size_t)(row0 + r) * NC + c] = acc;
        }
    } else {
        int lane = threadIdx.x & 31;
        int n = (blockIdx.x - GEMM_BLOCKS) * 8 + (threadIdx.x >> 5);
        if (n < NN) lpa_body(n, lane, lpa_in, lpa_out, offsets, pl);
    }
}

// ---------------- launch ----------------

extern "C" void kernel_launch(void* const* d_in, const int* in_sizes, int n_in,
                              void* d_out, int out_size) {
    const float* x    = (const float*)d_in[0];
    const void*  ei   = d_in[1];
    const void*  y    = d_in[2];
    const void*  mask = d_in[3];
    const float* ew   = (const float*)d_in[4];
    const float* W    = (const float*)d_in[5];
    const float* b    = (const float*)d_in[6];
    float* out = (float*)d_out;
    float* x_out   = out;             // [NN, NC]
    float* lpa_out = out + NN * NC;   // [NN, NC]

    static float* s = nullptr;
    if (s == nullptr) {
        void* p = nullptr;
        cudaGetSymbolAddress(&p, g_scratch);
        s = (float*)p;
    }
    float* deg     = s + OFF_DEG;
    float* dinv    = s + OFF_DINV;
    int*   counts  = (int*)(s + OFF_COUNTS);
    int*   cursor  = (int*)(s + OFF_CURSOR);
    int*   offsets = (int*)(s + OFF_OFFSETS);
    int*   flags   = (int*)(s + OFF_FLAGS);
    int2*  ps      = (int2*)(s + OFF_PAIR_SGC);
    int2*  pl      = (int2*)(s + OFF_PAIR_LPA);
    float* h0      = s + OFF_H0;
    float* h1      = s + OFF_H1;
    float* l0      = s + OFF_L0;
    float* l1      = s + OFF_L1;

    const int TB = 256;
    int gN = (NN + TB - 1) / TB;
    int gE = (NE + TB - 1) / TB;

    // ---- CSR build + sniff (flags owned by block 0 of init) ----
    init_sniff_kernel<<<gN, TB>>>(deg, counts, flags, ei, y, mask);
    deg_count_kernel<<<gE, TB>>>(ei, ew, deg, counts, flags);
    dinv_kernel<<<gN, TB>>>(deg, dinv);
    scan_kernel<<<1, 1024>>>(counts, offsets, cursor);
    fill_lpainit_kernel<<<FILL_BLOCKS + LINIT_BLOCKS, TB>>>(
        ei, ew, dinv, cursor, ps, pl, y, mask, l0, flags);

    // ---- fused: SGC pass k + LPA iter k run concurrently ----
    prop_pair_kernel<<<2 * PROP_BLOCKS, TB>>>(x,  h0, l0, l1, dinv, offsets, ps, pl);
    prop_pair_kernel<<<2 * PROP_BLOCKS, TB>>>(h0, h1, l1, l0, dinv, offsets, ps, pl);
    gemm_lpa_kernel<<<GEMM_BLOCKS + PROP_BLOCKS, TB>>>(
        h1, W, b, x_out, l0, lpa_out, offsets, pl);

    (void)in_sizes; (void)n_in; (void)out_size;
}

// round 6
// speedup vs baseline: 1.4551x; 1.3301x over previous
#include <cuda_runtime.h>
#include <cuda_bf16.h>
#include <cstdint>

#define NN 50000
#define NE 800000
#define NF 96
#define NC 40

#define SCAN_TB 256
#define SCAN_BLOCKS ((NN + SCAN_TB - 1) / SCAN_TB)   // 196

// ---------------- flat static device scratch ----------------
#define OFF_DEG      0
#define OFF_DINV     (OFF_DEG + NN)
#define OFF_COUNTS   (OFF_DINV + NN)
#define OFF_CURSOR   (OFF_COUNTS + NN)
#define OFF_OFFSETS  (OFF_CURSOR + NN)              // NN+1 ints
#define OFF_FLAGS    (OFF_OFFSETS + NN + 8)         // 4 ints
#define OFF_BSUM     (OFF_FLAGS + 8)                // 256 ints (block sums/prefixes)
#define OFF_PAIR_SGC (OFF_BSUM + 256)               // NE int2 (src, norm)
#define OFF_PAIR_LPA (OFF_PAIR_SGC + 2 * NE)        // NE int2 (src, ew)
#define OFF_H0       (OFF_PAIR_LPA + 2 * NE)
#define OFF_H1       (OFF_H0 + NN * NF)
#define OFF_L0       (OFF_H1 + NN * NF)
#define OFF_L1       (OFF_L0 + NN * NC)
#define SCRATCH_ELEMS (OFF_L1 + NN * NC + 64)

__device__ __align__(256) float g_scratch[SCRATCH_ELEMS];

// flags[0]: edge_index is int64; flags[1]: mask is 4-byte; flags[2]: y is int64
__device__ __forceinline__ int load_idx(const void* p, long long i, int is64) {
    return is64 ? (int)((const long long*)p)[i] : ((const int*)p)[i];
}

// ---------------- init + dtype sniff ----------------
__global__ void init_sniff_kernel(float* __restrict__ deg, int* __restrict__ counts,
                                  int* __restrict__ flags,
                                  const void* __restrict__ ei,
                                  const void* __restrict__ y,
                                  const void* __restrict__ mask) {
    int i = blockIdx.x * blockDim.x + threadIdx.x;
    if (i < NN) { deg[i] = 1.0f; counts[i] = 0; }

    if (blockIdx.x == 0) {
        __shared__ int narrow[3];
        int tid = threadIdx.x;
        if (tid < 3) narrow[tid] = 0;
        __syncthreads();
        const int* ei32 = (const int*)ei;
        const int* y32  = (const int*)y;
        const unsigned char* m8 = (const unsigned char*)mask;
        if (ei32[2 * tid + 1] != 0) narrow[0] = 1;
        if (y32[2 * tid + 1]  != 0) narrow[2] = 1;
        for (int t = tid; t < 4096; t += 256)
            if ((t & 3) != 0 && m8[t] != 0) narrow[1] = 1;
        __syncthreads();
        if (tid < 3) flags[tid] = narrow[tid] ? 0 : 1;
    }
}

__global__ void deg_count_kernel(const void* __restrict__ ei,
                                 const float* __restrict__ ew,
                                 float* __restrict__ deg,
                                 int* __restrict__ counts,
                                 const int* __restrict__ flags) {
    int e = blockIdx.x * blockDim.x + threadIdx.x;
    if (e < NE) {
        int c = load_idx(ei, (long long)NE + e, flags[0]);
        if ((unsigned)c < NN) {
            atomicAdd(&deg[c], ew[e]);
            atomicAdd(&counts[c], 1);
        }
    }
}

// ---- Phase A: per-block reduce of counts + fused dinv ----
__global__ void scanA_kernel(const int* __restrict__ counts,
                             const float* __restrict__ deg,
                             float* __restrict__ dinv,
                             int* __restrict__ bsum) {
    __shared__ int sh[SCAN_TB];
    int i = blockIdx.x * SCAN_TB + threadIdx.x;
    int v = (i < NN) ? counts[i] : 0;
    if (i < NN) dinv[i] = rsqrtf(deg[i]);
    sh[threadIdx.x] = v;
    __syncthreads();
    for (int off = SCAN_TB / 2; off > 0; off >>= 1) {
        if (threadIdx.x < off) sh[threadIdx.x] += sh[threadIdx.x + off];
        __syncthreads();
    }
    if (threadIdx.x == 0) bsum[blockIdx.x] = sh[0];
}

// ---- Phase B: exclusive scan of 196 block sums (single block) ----
__global__ void scanB_kernel(int* __restrict__ bsum, int* __restrict__ offsets) {
    __shared__ int sh[SCAN_TB];
    int t = threadIdx.x;
    int v = (t < SCAN_BLOCKS) ? bsum[t] : 0;
    sh[t] = v;
    __syncthreads();
    for (int off = 1; off < SCAN_TB; off <<= 1) {
        int u = (t >= off) ? sh[t - off] : 0;
        __syncthreads();
        sh[t] += u;
        __syncthreads();
    }
    if (t < SCAN_BLOCKS) bsum[t] = sh[t] - v;           // exclusive prefix
    if (t == SCAN_BLOCKS - 1) offsets[NN] = sh[t];      // total
}

// ---- Phase C: local scan + add block prefix -> offsets, cursor ----
__global__ void scanC_kernel(const int* __restrict__ counts,
                             const int* __restrict__ bsum,
                             int* __restrict__ offsets,
                             int* __restrict__ cursor) {
    __shared__ int sh[SCAN_TB];
    int i = blockIdx.x * SCAN_TB + threadIdx.x;
    int v = (i < NN) ? counts[i] : 0;
    sh[threadIdx.x] = v;
    __syncthreads();
    for (int off = 1; off < SCAN_TB; off <<= 1) {
        int u = (threadIdx.x >= off) ? sh[threadIdx.x - off] : 0;
        __syncthreads();
        sh[threadIdx.x] += u;
        __syncthreads();
    }
    if (i < NN) {
        int excl = bsum[blockIdx.x] + sh[threadIdx.x] - v;
        offsets[i] = excl;
        cursor[i]  = excl;
    }
}

// ---- fill CSR (+ fused LPA one-hot init in trailing blocks) ----
#define FILL_BLOCKS  ((NE + 255) / 256)             // 3125
#define LINIT_BLOCKS ((NN * NC + 255) / 256)        // 7813

__global__ void fill_lpainit_kernel(const void* __restrict__ ei,
                                    const float* __restrict__ ew,
                                    const float* __restrict__ dinv,
                                    int* __restrict__ cursor,
                                    int2* __restrict__ ps,
                                    int2* __restrict__ pl,
                                    const void* __restrict__ y,
                                    const void* __restrict__ mask,
                                    float* __restrict__ l0,
                                    const int* __restrict__ flags) {
    if (blockIdx.x < FILL_BLOCKS) {
        int e = blockIdx.x * blockDim.x + threadIdx.x;
        if (e < NE) {
            int is64 = flags[0];
            int r = load_idx(ei, e, is64);
            int c = load_idx(ei, (long long)NE + e, is64);
            if ((unsigned)r < NN && (unsigned)c < NN) {
                int pos = atomicAdd(&cursor[c], 1);
                if ((unsigned)pos < NE) {
                    float w = ew[e];
                    ps[pos] = make_int2(r, __float_as_int(dinv[r] * w * dinv[c]));
                    pl[pos] = make_int2(r, __float_as_int(w));
                }
            }
        }
    } else {
        int idx = (blockIdx.x - FILL_BLOCKS) * blockDim.x + threadIdx.x;
        if (idx < NN * NC) {
            int n = idx / NC, c = idx % NC;
            int yv = load_idx(y, n, flags[2]);
            int mv = flags[1] ? ((const int*)mask)[n]
                              : (int)((const unsigned char*)mask)[n];
            l0[idx] = (mv != 0 && yv == c) ? 1.0f : 0.0f;
        }
    }
}

// ---------------- propagate bodies (warp per node, unroll x4) --------

__device__ __forceinline__ void sgc_body(int n, int lane,
                                         const float* __restrict__ in,
                                         float* __restrict__ out,
                                         const float* __restrict__ dinv,
                                         const int* __restrict__ offsets,
                                         const int2* __restrict__ pr) {
    float dii = dinv[n];
    dii *= dii;
    const float* rp = in + (size_t)n * NF;
    float a0 = dii * rp[lane];
    float a1 = dii * rp[lane + 32];
    float a2 = dii * rp[lane + 64];
    int e = offsets[n], end = offsets[n + 1];
    for (; e + 4 <= end; e += 4) {
        int2 p0 = pr[e], p1 = pr[e + 1], p2 = pr[e + 2], p3 = pr[e + 3];
        const float* q0 = in + (size_t)p0.x * NF;
        const float* q1 = in + (size_t)p1.x * NF;
        const float* q2 = in + (size_t)p2.x * NF;
        const float* q3 = in + (size_t)p3.x * NF;
        float w0 = __int_as_float(p0.y), w1 = __int_as_float(p1.y);
        float w2 = __int_as_float(p2.y), w3 = __int_as_float(p3.y);
        float b00 = q0[lane], b01 = q0[lane + 32], b02 = q0[lane + 64];
        float b10 = q1[lane], b11 = q1[lane + 32], b12 = q1[lane + 64];
        float b20 = q2[lane], b21 = q2[lane + 32], b22 = q2[lane + 64];
        float b30 = q3[lane], b31 = q3[lane + 32], b32 = q3[lane + 64];
        a0 += w0 * b00; a1 += w0 * b01; a2 += w0 * b02;
        a0 += w1 * b10; a1 += w1 * b11; a2 += w1 * b12;
        a0 += w2 * b20; a1 += w2 * b21; a2 += w2 * b22;
        a0 += w3 * b30; a1 += w3 * b31; a2 += w3 * b32;
    }
    for (; e < end; e++) {
        int2 p = pr[e];
        float w = __int_as_float(p.y);
        const float* sp = in + (size_t)p.x * NF;
        a0 += w * sp[lane]; a1 += w * sp[lane + 32]; a2 += w * sp[lane + 64];
    }
    float* op = out + (size_t)n * NF;
    op[lane] = a0; op[lane + 32] = a1; op[lane + 64] = a2;
}

__device__ __forceinline__ void lpa_body(int n, int lane,
                                         const float* __restrict__ in,
                                         float* __restrict__ out,
                                         const int* __restrict__ offsets,
                                         const int2* __restrict__ pr) {
    float a0 = 0.0f, a1 = 0.0f;
    int e = offsets[n], end = offsets[n + 1];
    for (; e + 4 <= end; e += 4) {
        int2 p0 = pr[e], p1 = pr[e + 1], p2 = pr[e + 2], p3 = pr[e + 3];
        const float* q0 = in + (size_t)p0.x * NC;
        const float* q1 = in + (size_t)p1.x * NC;
        const float* q2 = in + (size_t)p2.x * NC;
        const float* q3 = in + (size_t)p3.x * NC;
        float w0 = __int_as_float(p0.y), w1 = __int_as_float(p1.y);
        float w2 = __int_as_float(p2.y), w3 = __int_as_float(p3.y);
        float b0 = q0[lane], b1 = q1[lane], b2 = q2[lane], b3 = q3[lane];
        float c0 = 0.f, c1 = 0.f, c2 = 0.f, c3 = 0.f;
        if (lane < 8) {
            c0 = q0[32 + lane]; c1 = q1[32 + lane];
            c2 = q2[32 + lane]; c3 = q3[32 + lane];
        }
        a0 += w0 * b0 + w1 * b1 + w2 * b2 + w3 * b3;
        a1 += w0 * c0 + w1 * c1 + w2 * c2 + w3 * c3;
    }
    for (; e < end; e++) {
        int2 p = pr[e];
        float w = __int_as_float(p.y);
        const float* sp = in + (size_t)p.x * NC;
        a0 += w * sp[lane];
        if (lane < 8) a1 += w * sp[32 + lane];
    }
    float* op = out + (size_t)n * NC;
    op[lane] = a0;
    if (lane < 8) op[32 + lane] = a1;
}

// ---------------- fused role kernels ----------------
#define PROP_BLOCKS ((NN * 32 + 255) / 256)   // 6250

__global__ void prop_pair_kernel(const float* __restrict__ sgc_in,
                                 float* __restrict__ sgc_out,
                                 const float* __restrict__ lpa_in,
                                 float* __restrict__ lpa_out,
                                 const float* __restrict__ dinv,
                                 const int* __restrict__ offsets,
                                 const int2* __restrict__ ps,
                                 const int2* __restrict__ pl) {
    int lane = threadIdx.x & 31;
    int wib  = threadIdx.x >> 5;
    if (blockIdx.x < PROP_BLOCKS) {
        int n = blockIdx.x * 8 + wib;
        if (n < NN) sgc_body(n, lane, sgc_in, sgc_out, dinv, offsets, ps);
    } else {
        int n = (blockIdx.x - PROP_BLOCKS) * 8 + wib;
        if (n < NN) lpa_body(n, lane, lpa_in, lpa_out, offsets, pl);
    }
}

#define GEMM_ROWS 32
#define GEMM_BLOCKS ((NN + GEMM_ROWS - 1) / GEMM_ROWS)   // 1563

__global__ void gemm_lpa_kernel(const float* __restrict__ h,
                                const float* __restrict__ W,
                                const float* __restrict__ b,
                                float* __restrict__ x_out,
                                const float* __restrict__ lpa_in,
                                float* __restrict__ lpa_out,
                                const int* __restrict__ offsets,
                                const int2* __restrict__ pl) {
    __shared__ float sW[NF * NC];
    __shared__ float sH[GEMM_ROWS * NF];
    if (blockIdx.x < GEMM_BLOCKS) {
        int tid = threadIdx.x;
        int row0 = blockIdx.x * GEMM_ROWS;
        for (int i = tid; i < NF * NC; i += 256) sW[i] = W[i];
        int nrows = min(GEMM_ROWS, NN - row0);
        int nelem = nrows * NF;
        const float* hp = h + (size_t)row0 * NF;
        for (int i = tid; i < nelem; i += 256) sH[i] = hp[i];
        __syncthreads();
        int nout = nrows * NC;
        for (int o = tid; o < nout; o += 256) {
            int r = o / NC, c = o % NC;
            float acc = b[c];
            const float* hr = &sH[r * NF];
            #pragma unroll 8
            for (int k = 0; k < NF; k++) acc += hr[k] * sW[k * NC + c];
            x_out[(size_t)(row0 + r) * NC + c] = acc;
        }
    } else {
        int lane = threadIdx.x & 31;
        int n = (blockIdx.x - GEMM_BLOCKS) * 8 + (threadIdx.x >> 5);
        if (n < NN) lpa_body(n, lane, lpa_in, lpa_out, offsets, pl);
    }
}

// ---------------- launch ----------------

extern "C" void kernel_launch(void* const* d_in, const int* in_sizes, int n_in,
                              void* d_out, int out_size) {
    const float* x    = (const float*)d_in[0];
    const void*  ei   = d_in[1];
    const void*  y    = d_in[2];
    const void*  mask = d_in[3];
    const float* ew   = (const float*)d_in[4];
    const float* W    = (const float*)d_in[5];
    const float* b    = (const float*)d_in[6];
    float* out = (float*)d_out;
    float* x_out   = out;
    float* lpa_out = out + NN * NC;

    static float* s = nullptr;
    if (s == nullptr) {
        void* p = nullptr;
        cudaGetSymbolAddress(&p, g_scratch);
        s = (float*)p;
    }
    float* deg     = s + OFF_DEG;
    float* dinv    = s + OFF_DINV;
    int*   counts  = (int*)(s + OFF_COUNTS);
    int*   cursor  = (int*)(s + OFF_CURSOR);
    int*   offsets = (int*)(s + OFF_OFFSETS);
    int*   flags   = (int*)(s + OFF_FLAGS);
    int*   bsum    = (int*)(s + OFF_BSUM);
    int2*  ps      = (int2*)(s + OFF_PAIR_SGC);
    int2*  pl      = (int2*)(s + OFF_PAIR_LPA);
    float* h0      = s + OFF_H0;
    float* h1      = s + OFF_H1;
    float* l0      = s + OFF_L0;
    float* l1      = s + OFF_L1;

    const int TB = 256;
    int gN = (NN + TB - 1) / TB;
    int gE = (NE + TB - 1) / TB;

    // ---- CSR build + sniff ----
    init_sniff_kernel<<<gN, TB>>>(deg, counts, flags, ei, y, mask);
    deg_count_kernel<<<gE, TB>>>(ei, ew, deg, counts, flags);
    scanA_kernel<<<SCAN_BLOCKS, SCAN_TB>>>(counts, deg, dinv, bsum);
    scanB_kernel<<<1, SCAN_TB>>>(bsum, offsets);
    scanC_kernel<<<SCAN_BLOCKS, SCAN_TB>>>(counts, bsum, offsets, cursor);
    fill_lpainit_kernel<<<FILL_BLOCKS + LINIT_BLOCKS, TB>>>(
        ei, ew, dinv, cursor, ps, pl, y, mask, l0, flags);

    // ---- fused: SGC pass k + LPA iter k run concurrently ----
    prop_pair_kernel<<<2 * PROP_BLOCKS, TB>>>(x,  h0, l0, l1, dinv, offsets, ps, pl);
    prop_pair_kernel<<<2 * PROP_BLOCKS, TB>>>(h0, h1, l1, l0, dinv, offsets, ps, pl);
    gemm_lpa_kernel<<<GEMM_BLOCKS + PROP_BLOCKS, TB>>>(
        h1, W, b, x_out, l0, lpa_out, offsets, pl);

    (void)in_sizes; (void)n_in; (void)out_size;
}

// round 7
// speedup vs baseline: 1.5200x; 1.0446x over previous
#include <cuda_runtime.h>
#include <cuda_bf16.h>
#include <cstdint>

#define NN 50000
#define NE 800000
#define NF 96
#define NC 40

#define SCAN_TB 256
#define SCAN_BLOCKS ((NN + SCAN_TB - 1) / SCAN_TB)   // 196

// ---------------- flat static device scratch ----------------
#define OFF_DEG      0
#define OFF_DINV     (OFF_DEG + NN)
#define OFF_COUNTS   (OFF_DINV + NN)
#define OFF_CURSOR   (OFF_COUNTS + NN)
#define OFF_OFFSETS  (OFF_CURSOR + NN)              // NN+1 ints
#define OFF_FLAGS    (OFF_OFFSETS + NN + 8)         // 4 ints
#define OFF_BSUM     (OFF_FLAGS + 8)                // 256 ints
#define OFF_PAIR_SGC (OFF_BSUM + 256)               // NE int2 (src, norm)
#define OFF_PAIR_LPA (OFF_PAIR_SGC + 2 * NE)        // NE int2 (src, ew)
#define OFF_Z0       (OFF_PAIR_LPA + 2 * NE)        // NN*NC
#define OFF_Z1       (OFF_Z0 + NN * NC)
#define OFF_L0       (OFF_Z1 + NN * NC)
#define OFF_L1       (OFF_L0 + NN * NC)
#define SCRATCH_ELEMS (OFF_L1 + NN * NC + 64)

__device__ __align__(256) float g_scratch[SCRATCH_ELEMS];

// flags[0]: edge_index is int64; flags[1]: mask is 4-byte; flags[2]: y is int64
__device__ __forceinline__ int load_idx(const void* p, long long i, int is64) {
    return is64 ? (int)((const long long*)p)[i] : ((const int*)p)[i];
}

// ---------------- K1: init + sniff + gemm (z = x @ W, NO bias) ----------------
#define GEMM_ROWS 32
#define GEMM_BLOCKS ((NN + GEMM_ROWS - 1) / GEMM_ROWS)   // 1563
#define INIT_BLOCKS ((NN + 255) / 256)                    // 196

__global__ void init_sniff_gemm_kernel(float* __restrict__ deg,
                                       int* __restrict__ counts,
                                       int* __restrict__ flags,
                                       const void* __restrict__ ei,
                                       const void* __restrict__ y,
                                       const void* __restrict__ mask,
                                       const float* __restrict__ x,
                                       const float* __restrict__ W,
                                       float* __restrict__ z) {
    if (blockIdx.x < INIT_BLOCKS) {
        int i = blockIdx.x * blockDim.x + threadIdx.x;
        if (i < NN) { deg[i] = 1.0f; counts[i] = 0; }
        if (blockIdx.x == 0) {
            __shared__ int narrow[3];
            int tid = threadIdx.x;
            if (tid < 3) narrow[tid] = 0;
            __syncthreads();
            const int* ei32 = (const int*)ei;
            const int* y32  = (const int*)y;
            const unsigned char* m8 = (const unsigned char*)mask;
            if (ei32[2 * tid + 1] != 0) narrow[0] = 1;
            if (y32[2 * tid + 1]  != 0) narrow[2] = 1;
            for (int t = tid; t < 4096; t += 256)
                if ((t & 3) != 0 && m8[t] != 0) narrow[1] = 1;
            __syncthreads();
            if (tid < 3) flags[tid] = narrow[tid] ? 0 : 1;
        }
    } else {
        __shared__ float sW[NF * NC];          // 15360 B
        __shared__ float sH[GEMM_ROWS * NF];   // 12288 B
        int tid = threadIdx.x;
        int row0 = (blockIdx.x - INIT_BLOCKS) * GEMM_ROWS;
        for (int i = tid; i < NF * NC; i += 256) sW[i] = W[i];
        int nrows = min(GEMM_ROWS, NN - row0);
        int nelem = nrows * NF;
        const float* hp = x + (size_t)row0 * NF;
        for (int i = tid; i < nelem; i += 256) sH[i] = hp[i];
        __syncthreads();
        int nout = nrows * NC;
        for (int o = tid; o < nout; o += 256) {
            int r = o / NC, c = o % NC;
            float acc = 0.0f;
            const float* hr = &sH[r * NF];
            #pragma unroll 8
            for (int k = 0; k < NF; k++) acc += hr[k] * sW[k * NC + c];
            z[(size_t)(row0 + r) * NC + c] = acc;
        }
    }
}

__global__ void deg_count_kernel(const void* __restrict__ ei,
                                 const float* __restrict__ ew,
                                 float* __restrict__ deg,
                                 int* __restrict__ counts,
                                 const int* __restrict__ flags) {
    int e = blockIdx.x * blockDim.x + threadIdx.x;
    if (e < NE) {
        int c = load_idx(ei, (long long)NE + e, flags[0]);
        if ((unsigned)c < NN) {
            atomicAdd(&deg[c], ew[e]);
            atomicAdd(&counts[c], 1);
        }
    }
}

// ---- Phase A: per-block reduce of counts + fused dinv ----
__global__ void scanA_kernel(const int* __restrict__ counts,
                             const float* __restrict__ deg,
                             float* __restrict__ dinv,
                             int* __restrict__ bsum) {
    __shared__ int sh[SCAN_TB];
    int i = blockIdx.x * SCAN_TB + threadIdx.x;
    int v = (i < NN) ? counts[i] : 0;
    if (i < NN) dinv[i] = rsqrtf(deg[i]);
    sh[threadIdx.x] = v;
    __syncthreads();
    for (int off = SCAN_TB / 2; off > 0; off >>= 1) {
        if (threadIdx.x < off) sh[threadIdx.x] += sh[threadIdx.x + off];
        __syncthreads();
    }
    if (threadIdx.x == 0) bsum[blockIdx.x] = sh[0];
}

// ---- Phase B: exclusive scan of block sums ----
__global__ void scanB_kernel(int* __restrict__ bsum, int* __restrict__ offsets) {
    __shared__ int sh[SCAN_TB];
    int t = threadIdx.x;
    int v = (t < SCAN_BLOCKS) ? bsum[t] : 0;
    sh[t] = v;
    __syncthreads();
    for (int off = 1; off < SCAN_TB; off <<= 1) {
        int u = (t >= off) ? sh[t - off] : 0;
        __syncthreads();
        sh[t] += u;
        __syncthreads();
    }
    if (t < SCAN_BLOCKS) bsum[t] = sh[t] - v;
    if (t == SCAN_BLOCKS - 1) offsets[NN] = sh[t];
}

// ---- Phase C: local scan + block prefix ----
__global__ void scanC_kernel(const int* __restrict__ counts,
                             const int* __restrict__ bsum,
                             int* __restrict__ offsets,
                             int* __restrict__ cursor) {
    __shared__ int sh[SCAN_TB];
    int i = blockIdx.x * SCAN_TB + threadIdx.x;
    int v = (i < NN) ? counts[i] : 0;
    sh[threadIdx.x] = v;
    __syncthreads();
    for (int off = 1; off < SCAN_TB; off <<= 1) {
        int u = (threadIdx.x >= off) ? sh[threadIdx.x - off] : 0;
        __syncthreads();
        sh[threadIdx.x] += u;
        __syncthreads();
    }
    if (i < NN) {
        int excl = bsum[blockIdx.x] + sh[threadIdx.x] - v;
        offsets[i] = excl;
        cursor[i]  = excl;
    }
}

// ---- fill CSR (+ fused LPA one-hot init) ----
#define FILL_BLOCKS  ((NE + 255) / 256)
#define LINIT_BLOCKS ((NN * NC + 255) / 256)

__global__ void fill_lpainit_kernel(const void* __restrict__ ei,
                                    const float* __restrict__ ew,
                                    const float* __restrict__ dinv,
                                    int* __restrict__ cursor,
                                    int2* __restrict__ ps,
                                    int2* __restrict__ pl,
                                    const void* __restrict__ y,
                                    const void* __restrict__ mask,
                                    float* __restrict__ l0,
                                    const int* __restrict__ flags) {
    if (blockIdx.x < FILL_BLOCKS) {
        int e = blockIdx.x * blockDim.x + threadIdx.x;
        if (e < NE) {
            int is64 = flags[0];
            int r = load_idx(ei, e, is64);
            int c = load_idx(ei, (long long)NE + e, is64);
            if ((unsigned)r < NN && (unsigned)c < NN) {
                int pos = atomicAdd(&cursor[c], 1);
                if ((unsigned)pos < NE) {
                    float w = ew[e];
                    ps[pos] = make_int2(r, __float_as_int(dinv[r] * w * dinv[c]));
                    pl[pos] = make_int2(r, __float_as_int(w));
                }
            }
        }
    } else {
        int idx = (blockIdx.x - FILL_BLOCKS) * blockDim.x + threadIdx.x;
        if (idx < NN * NC) {
            int n = idx / NC, c = idx % NC;
            int yv = load_idx(y, n, flags[2]);
            int mv = flags[1] ? ((const int*)mask)[n]
                              : (int)((const unsigned char*)mask)[n];
            l0[idx] = (mv != 0 && yv == c) ? 1.0f : 0.0f;
        }
    }
}

// ---------------- unified 40-wide propagate body ----------------
// Warp per node. Lanes 0-29 split into 3 groups of 10; each group handles one
// edge, each lane one float4 of the 160B source row. 2 edge-triples per iter
// for MLP ~6. Shfl-combine partials, lanes 0-9 write the output row.
template <bool SELF, bool BIAS>
__device__ __forceinline__ void prop40(int n, int lane,
                                       const float* __restrict__ in,
                                       float* __restrict__ out,
                                       const float* __restrict__ dinv,
                                       const float* __restrict__ bias,
                                       const int* __restrict__ offsets,
                                       const int2* __restrict__ pr) {
    int grp = lane / 10;           // 0..2 active; lanes 30,31 idle
    int sub = lane - grp * 10;     // 0..9
    bool active = (lane < 30);
    float4 acc = make_float4(0.f, 0.f, 0.f, 0.f);
    int beg = offsets[n], end = offsets[n + 1];
    int e = beg;
    for (; e + 6 <= end; e += 6) {
        int2 pa, pb;
        float wa = 0.f, wb = 0.f; int sa = 0, sb = 0;
        if (active) {
            pa = pr[e + grp];     sa = pa.x; wa = __int_as_float(pa.y);
            pb = pr[e + 3 + grp]; sb = pb.x; wb = __int_as_float(pb.y);
        }
        float4 va = make_float4(0.f,0.f,0.f,0.f), vb = va;
        if (wa != 0.f) va = ((const float4*)(in + (size_t)sa * NC))[sub];
        if (wb != 0.f) vb = ((const float4*)(in + (size_t)sb * NC))[sub];
        acc.x += wa * va.x + wb * vb.x;
        acc.y += wa * va.y + wb * vb.y;
        acc.z += wa * va.z + wb * vb.z;
        acc.w += wa * va.w + wb * vb.w;
    }
    for (; e < end; e += 3) {
        int idx = e + grp;
        float w = 0.f; int s = 0;
        if (active && idx < end) {
            int2 p = pr[idx]; s = p.x; w = __int_as_float(p.y);
        }
        if (w != 0.f) {
            float4 v = ((const float4*)(in + (size_t)s * NC))[sub];
            acc.x += w * v.x; acc.y += w * v.y; acc.z += w * v.z; acc.w += w * v.w;
        }
    }
    // combine partials from lane+10, lane+20 (valid on lanes 0-9)
    unsigned m = 0xFFFFFFFFu;
    float t1, t2;
    t1 = __shfl_sync(m, acc.x, lane + 10); t2 = __shfl_sync(m, acc.x, lane + 20);
    acc.x += t1 + t2;
    t1 = __shfl_sync(m, acc.y, lane + 10); t2 = __shfl_sync(m, acc.y, lane + 20);
    acc.y += t1 + t2;
    t1 = __shfl_sync(m, acc.z, lane + 10); t2 = __shfl_sync(m, acc.z, lane + 20);
    acc.z += t1 + t2;
    t1 = __shfl_sync(m, acc.w, lane + 10); t2 = __shfl_sync(m, acc.w, lane + 20);
    acc.w += t1 + t2;

    if (lane < 10) {
        if (SELF) {
            float dii = dinv[n]; dii *= dii;
            float4 v = ((const float4*)(in + (size_t)n * NC))[lane];
            acc.x += dii * v.x; acc.y += dii * v.y;
            acc.z += dii * v.z; acc.w += dii * v.w;
        }
        if (BIAS) {
            float4 bb = ((const float4*)bias)[lane];
            acc.x += bb.x; acc.y += bb.y; acc.z += bb.z; acc.w += bb.w;
        }
        ((float4*)(out + (size_t)n * NC))[lane] = acc;
    }
}

#define PROP_BLOCKS ((NN + 7) / 8)    // 8 warps/block, warp per node: 6250

// pair1: SGC hop1 (z0->z1) + LPA iter1 (l0->l1)
// pair2: SGC hop2+bias (z1->x_out) + LPA iter2 (l1->l0)
template <bool LAST>
__global__ void prop_pair_kernel(const float* __restrict__ sgc_in,
                                 float* __restrict__ sgc_out,
                                 const float* __restrict__ lpa_in,
                                 float* __restrict__ lpa_out,
                                 const float* __restrict__ dinv,
                                 const float* __restrict__ bias,
                                 const int* __restrict__ offsets,
                                 const int2* __restrict__ ps,
                                 const int2* __restrict__ pl) {
    int lane = threadIdx.x & 31;
    int wib  = threadIdx.x >> 5;
    if (blockIdx.x < PROP_BLOCKS) {
        int n = blockIdx.x * 8 + wib;
        if (n < NN) prop40<true, LAST>(n, lane, sgc_in, sgc_out, dinv, bias, offsets, ps);
    } else {
        int n = (blockIdx.x - PROP_BLOCKS) * 8 + wib;
        if (n < NN) prop40<false, false>(n, lane, lpa_in, lpa_out, dinv, bias, offsets, pl);
    }
}

// final LPA iter3 (l0 -> lpa_out)
__global__ void lpa_final_kernel(const float* __restrict__ in,
                                 float* __restrict__ out,
                                 const int* __restrict__ offsets,
                                 const int2* __restrict__ pl) {
    int lane = threadIdx.x & 31;
    int n = blockIdx.x * 8 + (threadIdx.x >> 5);
    if (n < NN) prop40<false, false>(n, lane, in, out, nullptr, nullptr, offsets, pl);
}

// ---------------- launch ----------------

extern "C" void kernel_launch(void* const* d_in, const int* in_sizes, int n_in,
                              void* d_out, int out_size) {
    const float* x    = (const float*)d_in[0];
    const void*  ei   = d_in[1];
    const void*  y    = d_in[2];
    const void*  mask = d_in[3];
    const float* ew   = (const float*)d_in[4];
    const float* W    = (const float*)d_in[5];
    const float* b    = (const float*)d_in[6];
    float* out = (float*)d_out;
    float* x_out   = out;
    float* lpa_out = out + NN * NC;

    static float* s = nullptr;
    if (s == nullptr) {
        void* p = nullptr;
        cudaGetSymbolAddress(&p, g_scratch);
        s = (float*)p;
    }
    float* deg     = s + OFF_DEG;
    float* dinv    = s + OFF_DINV;
    int*   counts  = (int*)(s + OFF_COUNTS);
    int*   cursor  = (int*)(s + OFF_CURSOR);
    int*   offsets = (int*)(s + OFF_OFFSETS);
    int*   flags   = (int*)(s + OFF_FLAGS);
    int*   bsum    = (int*)(s + OFF_BSUM);
    int2*  ps      = (int2*)(s + OFF_PAIR_SGC);
    int2*  pl      = (int2*)(s + OFF_PAIR_LPA);
    float* z0      = s + OFF_Z0;
    float* z1      = s + OFF_Z1;
    float* l0      = s + OFF_L0;
    float* l1      = s + OFF_L1;

    const int TB = 256;
    int gE = (NE + TB - 1) / TB;

    // K1: init + sniff + z = x@W (gemm overlaps CSR build)
    init_sniff_gemm_kernel<<<INIT_BLOCKS + GEMM_BLOCKS, TB>>>(
        deg, counts, flags, ei, y, mask, x, W, z0);
    // K2-K6: CSR build
    deg_count_kernel<<<gE, TB>>>(ei, ew, deg, counts, flags);
    scanA_kernel<<<SCAN_BLOCKS, SCAN_TB>>>(counts, deg, dinv, bsum);
    scanB_kernel<<<1, SCAN_TB>>>(bsum, offsets);
    scanC_kernel<<<SCAN_BLOCKS, SCAN_TB>>>(counts, bsum, offsets, cursor);
    fill_lpainit_kernel<<<FILL_BLOCKS + LINIT_BLOCKS, TB>>>(
        ei, ew, dinv, cursor, ps, pl, y, mask, l0, flags);

    // K7: SGC hop1 + LPA iter1
    prop_pair_kernel<false><<<2 * PROP_BLOCKS, TB>>>(
        z0, z1, l0, l1, dinv, b, offsets, ps, pl);
    // K8: SGC hop2 (+bias -> x_out) + LPA iter2
    prop_pair_kernel<true><<<2 * PROP_BLOCKS, TB>>>(
        z1, x_out, l1, l0, dinv, b, offsets, ps, pl);
    // K9: LPA iter3 -> lpa_out
    lpa_final_kernel<<<PROP_BLOCKS, TB>>>(l0, lpa_out, offsets, pl);

    (void)in_sizes; (void)n_in; (void)out_size;
}